// round 10
// baseline (speedup 1.0000x reference)
#include <cuda_runtime.h>
#include <cuda_bf16.h>
#include <cstdint>

// Problem constants
namespace {
constexpr int kB  = 4;
constexpr int kT  = 4096;
constexpr int kC  = 1024;
constexpr int kHD = 64;
constexpr int kM  = kB * kT;            // 16384 rows
constexpr float kScale  = 0.125f;       // 1/sqrt(64)
constexpr float kNegBig = -1e30f;
}

// bf16 hi/lo split operands (all row-major [t][64])
__device__ __nv_bfloat16 g_qh[kM * kHD];
__device__ __nv_bfloat16 g_ql[kM * kHD];
__device__ __nv_bfloat16 g_kh[kM * kHD];
__device__ __nv_bfloat16 g_kl[kM * kHD];
__device__ __nv_bfloat16 g_vh[kM * kHD];
__device__ __nv_bfloat16 g_vl[kM * kHD];
// Pre-split TRANSPOSED weights Wt[3][64 n][1024 k]
__device__ __nv_bfloat16 g_wth[3 * kHD * kC];
__device__ __nv_bfloat16 g_wtl[3 * kHD * kC];

// ---------------------------------------------------------------------------
// Helpers
// ---------------------------------------------------------------------------
__device__ __forceinline__ uint32_t smem_u32(const void* p) {
  uint32_t a;
  asm("{ .reg .u64 t; cvta.to.shared.u64 t, %1; cvt.u32.u64 %0, t; }"
      : "=r"(a) : "l"(p));
  return a;
}
__device__ __forceinline__ uint32_t sw128(uint32_t off) {
  return off ^ ((off >> 3) & 0x70);
}
__device__ __forceinline__ void mma_bf16(float c[4], const uint32_t a[4],
                                         uint32_t b0, uint32_t b1) {
  asm volatile(
      "mma.sync.aligned.m16n8k16.row.col.f32.bf16.bf16.f32 "
      "{%0,%1,%2,%3}, {%4,%5,%6,%7}, {%8,%9}, {%0,%1,%2,%3};"
      : "+f"(c[0]), "+f"(c[1]), "+f"(c[2]), "+f"(c[3])
      : "r"(a[0]), "r"(a[1]), "r"(a[2]), "r"(a[3]), "r"(b0), "r"(b1));
}
__device__ __forceinline__ void ldsm_x4(uint32_t r[4], uint32_t addr) {
  asm volatile("ldmatrix.sync.aligned.m8n8.x4.shared.b16 {%0,%1,%2,%3}, [%4];"
               : "=r"(r[0]), "=r"(r[1]), "=r"(r[2]), "=r"(r[3]) : "r"(addr));
}
__device__ __forceinline__ void ldsm_x4t(uint32_t r[4], uint32_t addr) {
  asm volatile("ldmatrix.sync.aligned.m8n8.x4.trans.shared.b16 {%0,%1,%2,%3}, [%4];"
               : "=r"(r[0]), "=r"(r[1]), "=r"(r[2]), "=r"(r[3]) : "r"(addr));
}
__device__ __forceinline__ void cp16(uint32_t dst, const void* src) {
  asm volatile("cp.async.cg.shared.global [%0], [%1], 16;" :: "r"(dst),
               "l"(__cvta_generic_to_global(src)));
}
#define CP_COMMIT() asm volatile("cp.async.commit_group;" ::: "memory")
#define CP_WAIT(n)  asm volatile("cp.async.wait_group %0;" :: "n"(n) : "memory")
__device__ __forceinline__ void barteam(int id) {
  asm volatile("bar.sync %0, 128;" :: "r"(id) : "memory");
}

// Pack two fp32 into bf16x2 (lower half = a0) plus the residual bf16x2.
__device__ __forceinline__ void split_pack(float a0, float a1, uint32_t& h,
                                           uint32_t& l) {
  asm("cvt.rn.bf16x2.f32 %0, %1, %2;" : "=r"(h) : "f"(a1), "f"(a0));
  float f0 = __uint_as_float(h << 16);
  float f1 = __uint_as_float(h & 0xFFFF0000u);
  asm("cvt.rn.bf16x2.f32 %0, %1, %2;" : "=r"(l) : "f"(a1 - f1), "f"(a0 - f0));
}

// ---------------------------------------------------------------------------
// Kernel D: no-op (shifts the ncu capture window onto proj_kernel).
// ---------------------------------------------------------------------------
__global__ void dummy_kernel() {}

// ---------------------------------------------------------------------------
// Kernel 0: W pre-split + transpose. Wt[h][n][k] hi/lo. grid=96, block=256.
// ---------------------------------------------------------------------------
__global__ __launch_bounds__(256) void wsplit_kernel(
    const float* __restrict__ Wq, const float* __restrict__ Wk,
    const float* __restrict__ Wv) {
  const int idx = blockIdx.x * 256 + threadIdx.x;   // 24576 total
  const int h3 = idx >> 13;
  const int rem = idx & 8191;
  const int kg = rem >> 6;        // k-group (8 k's)
  const int n = rem & 63;
  const float* W = (h3 == 0) ? Wq : (h3 == 1) ? Wk : Wv;
  const int k0 = kg * 8;
  uint32_t h[4], l[4];
#pragma unroll
  for (int j = 0; j < 4; ++j) {
    const float a0 = W[(size_t)(k0 + 2 * j) * kHD + n];
    const float a1 = W[(size_t)(k0 + 2 * j + 1) * kHD + n];
    split_pack(a0, a1, h[j], l[j]);
  }
  const size_t base = (size_t)h3 * kHD * kC + (size_t)n * kC + k0;
  *(uint4*)(g_wth + base) = make_uint4(h[0], h[1], h[2], h[3]);
  *(uint4*)(g_wtl + base) = make_uint4(l[0], l[1], l[2], l[3]);
}

// ---------------------------------------------------------------------------
// Kernel 1: QKV projection. grid = kM/128, block = 256 (8 warps x 16 rows).
// B = Wt (n-major) via NON-trans ldsm_x4; 3-stage cp.async W ring (proven
// R8 discipline: one barrier per chunk, issue kc+2 after the barrier);
// x raw-prefetch in regs.
// ---------------------------------------------------------------------------
namespace {
constexpr int kProjStage = 49152;            // 6 tiles x 8KB (3 heads x hi/lo)
constexpr int kProjSmem  = 3 * kProjStage;   // 147456 (proven size)
}

__global__ __launch_bounds__(256, 1) void proj_kernel(const float* __restrict__ x) {
  extern __shared__ char smem[];
  const uint32_t sb = smem_u32(smem);
  const int tid = threadIdx.x;
  const int w = tid >> 5, lane = tid & 31;
  const int g = lane >> 2, tg = lane & 3;
  const int row0 = blockIdx.x * 128;
  // non-trans ldsm per-lane address parts (attn-K pattern)
  const int krow = lane & 7;
  const int kk8 = ((lane >> 3) & 1) * 16;
  const int kjb = lane >> 4;

  auto issue_w = [&](int kc, int stage) {
    const uint32_t sbase = sb + stage * kProjStage;
#pragma unroll
    for (int rep = 0; rep < 12; ++rep) {
      const int e = tid + rep * 256;
      const int ch = e & 7, n = (e >> 3) & 63, rest = e >> 9;
      const int h3 = rest >> 1, hl = rest & 1;
      const __nv_bfloat16* src = (hl ? g_wtl : g_wth) +
          ((size_t)h3 * kHD + n) * kC + kc * 64 + ch * 8;
      cp16(sbase + h3 * 16384 + hl * 8192 + sw128(n * 128 + ch * 16), src);
    }
    CP_COMMIT();
  };

  const int r1 = row0 + w * 16 + g;
  const float* xrow1 = x + (size_t)r1 * kC + tg * 2;
  const float* xrow2 = xrow1 + (size_t)8 * kC;

  auto load_xraw = [&](float2 xr[16], int kc) {
#pragma unroll
    for (int ks = 0; ks < 4; ++ks) {
      const float* p1 = xrow1 + kc * 64 + ks * 16;
      const float* p2 = xrow2 + kc * 64 + ks * 16;
      xr[ks * 4 + 0] = *(const float2*)p1;
      xr[ks * 4 + 1] = *(const float2*)p2;
      xr[ks * 4 + 2] = *(const float2*)(p1 + 8);
      xr[ks * 4 + 3] = *(const float2*)(p2 + 8);
    }
  };

  float acc[24][4] = {};
  float2 xraw[16];

  issue_w(0, 0);
  issue_w(1, 1);
  load_xraw(xraw, 0);

  int st = 0;
  for (int kc = 0; kc < 16; ++kc) {
    // ---- split current x raw into A fragments; prefetch next raw ----
    uint32_t xh[4][4], xl[4][4];
#pragma unroll
    for (int p = 0; p < 16; ++p)
      split_pack(xraw[p].x, xraw[p].y, xh[p >> 2][p & 3], xl[p >> 2][p & 3]);
    if (kc + 1 < 16) load_xraw(xraw, kc + 1);

    if (kc < 15) CP_WAIT(1); else CP_WAIT(0);
    __syncthreads();

    // issue stage kc+2 -> slot (st+2)%3 == (kc-1)%3; its readers cleared the
    // barrier above (program order), so no trailing sync is needed.
    if (kc + 2 < 16) issue_w(kc + 2, (st + 2 >= 3) ? st - 1 : st + 2);

    const uint32_t sbase = sb + st * kProjStage;
#pragma unroll
    for (int h3 = 0; h3 < 3; ++h3) {
#pragma unroll
      for (int nb2 = 0; nb2 < 4; ++nb2) {
        float* a0 = acc[h3 * 8 + 2 * nb2];
        float* a1 = acc[h3 * 8 + 2 * nb2 + 1];
#pragma unroll
        for (int ks = 0; ks < 4; ++ks) {
          const uint32_t off = sw128(
              (uint32_t)(((2 * nb2 + kjb) * 8 + krow) * 128 + ks * 32 + kk8));
          uint32_t bh[4], bl[4];
          ldsm_x4(bh, sbase + h3 * 16384 + off);
          ldsm_x4(bl, sbase + h3 * 16384 + 8192 + off);
          mma_bf16(a0, xh[ks], bh[0], bh[1]);
          mma_bf16(a0, xl[ks], bh[0], bh[1]);
          mma_bf16(a0, xh[ks], bl[0], bl[1]);
          mma_bf16(a1, xh[ks], bh[2], bh[3]);
          mma_bf16(a1, xl[ks], bh[2], bh[3]);
          mma_bf16(a1, xh[ks], bl[2], bl[3]);
        }
      }
    }
    st = (st + 1 == 3) ? 0 : st + 1;
  }

  // ---- epilogue: split fp32 accumulators to bf16 hi/lo gmem ----
  const int r2 = r1 + 8;
#pragma unroll
  for (int nb = 0; nb < 24; ++nb) {
    const int h3 = nb >> 3, col = (nb & 7) * 8 + tg * 2;
    __nv_bfloat16* hp = (h3 == 0) ? g_qh : (h3 == 1) ? g_kh : g_vh;
    __nv_bfloat16* lp = (h3 == 0) ? g_ql : (h3 == 1) ? g_kl : g_vl;
    uint32_t h, l;
    split_pack(acc[nb][0], acc[nb][1], h, l);
    *(uint32_t*)(hp + (size_t)r1 * kHD + col) = h;
    *(uint32_t*)(lp + (size_t)r1 * kHD + col) = l;
    split_pack(acc[nb][2], acc[nb][3], h, l);
    *(uint32_t*)(hp + (size_t)r2 * kHD + col) = h;
    *(uint32_t*)(lp + (size_t)r2 * kHD + col) = l;
  }
}

// ---------------------------------------------------------------------------
// Kernel 2: split-K causal flash attention with paired query tiles.
// (unchanged — verified; rel_err 1.4e-5)
// ---------------------------------------------------------------------------
namespace {
constexpr int aKV   = 0;
constexpr int aQH   = 131072;
constexpr int aQL   = 139264;
constexpr int aMADD = 147456;
constexpr int aM    = 148480;
constexpr int aL    = 148992;
constexpr int aOSC  = 149504;
constexpr int kAttnSmem = 165888;
}

__global__ __launch_bounds__(256) void attn_kernel(
    const int* __restrict__ pmask, float* __restrict__ out) {
  extern __shared__ char smem[];
  const uint32_t sb = smem_u32(smem);
  const int tid = threadIdx.x;
  const int team = tid >> 7;
  const int wt = tid & 127;
  const int w = wt >> 5, lane = wt & 31;
  const int g = lane >> 2, tg = lane & 3;
  const int b = blockIdx.y;
  const int bx = blockIdx.x;
  const int barid = 1 + team;

  const int krow = lane & 7;
  const int kk8 = ((lane >> 3) & 1) * 16;
  const int kjb = lane >> 4;
  const int vrow = (lane & 7) + ((lane >> 3) & 1) * 8;
  const int vnb = lane >> 4;

  auto issue_kv = [&](int s0n, int stage) {
    const uint32_t sbase = sb + aKV + team * 65536 + stage * 32768;
#pragma unroll
    for (int rep = 0; rep < 16; ++rep) {
      const int e = wt + rep * 128;
      const int which = e >> 9, rem = e & 511;
      const int j = rem >> 3, ch = rem & 7;
      const __nv_bfloat16* base =
          (which == 0) ? g_kh : (which == 1) ? g_kl : (which == 2) ? g_vh : g_vl;
      cp16(sbase + which * 8192 + sw128(j * 128 + ch * 16),
           base + (size_t)(b * kT + s0n + j) * kHD + ch * 8);
    }
    if (wt < 64)
      ((float*)(smem + aMADD + team * 512 + stage * 256))[wt] =
          (pmask[b * kT + s0n + wt] == 0) ? kNegBig : 0.0f;
    CP_COMMIT();
  };

#pragma unroll 1
  for (int phase = 0; phase < 2; ++phase) {
    const int qi = phase ? bx : (63 - bx);
    const int t0 = qi * 64;
    const int ntiles = qi + 1;
    const int qg1 = t0 + w * 16 + g;
    const int qg2 = qg1 + 8;

    __syncthreads();

    if (team < ntiles) issue_kv(team * 64, 0);

#pragma unroll
    for (int rep = 0; rep < 2; ++rep) {
      const int e = tid + rep * 256;
      const int j = e >> 3, ch = e & 7;
      const uint32_t sw = sw128((uint32_t)(j * 128 + ch * 16));
      const size_t goff = (size_t)(b * kT + t0 + j) * kHD + ch * 8;
      *(uint4*)(smem + aQH + sw) = *(const uint4*)(g_qh + goff);
      *(uint4*)(smem + aQL + sw) = *(const uint4*)(g_ql + goff);
    }
    __syncthreads();

    uint32_t qh[4][4], ql[4][4];
    {
      const int arow = w * 16 + (lane & 15);
      const int acb = lane >> 4;
#pragma unroll
      for (int ks = 0; ks < 4; ++ks) {
        const uint32_t off = sw128((uint32_t)(arow * 128 + ks * 32 + acb * 16));
        ldsm_x4(qh[ks], sb + aQH + off);
        ldsm_x4(ql[ks], sb + aQL + off);
      }
    }

    float O[8][4] = {};
    float m1 = kNegBig, m2 = kNegBig, l1 = 0.0f, l2 = 0.0f;

    for (int it = team; it < ntiles; it += 2) {
      const int s0 = it * 64;
      const int ord = it >> 1;
      if (it + 2 < ntiles) { issue_kv((it + 2) * 64, (ord + 1) & 1); CP_WAIT(1); }
      else CP_WAIT(0);
      barteam(barid);
      const uint32_t sbase = sb + aKV + team * 65536 + (ord & 1) * 32768;
      const float* madd =
          (const float*)(smem + aMADD + team * 512 + (ord & 1) * 256);

      float sc[8][4];
#pragma unroll
      for (int jb2 = 0; jb2 < 4; ++jb2) {
        float* s0p = sc[2 * jb2];
        float* s1p = sc[2 * jb2 + 1];
        s0p[0] = s0p[1] = s0p[2] = s0p[3] = 0.0f;
        s1p[0] = s1p[1] = s1p[2] = s1p[3] = 0.0f;
#pragma unroll
        for (int ks = 0; ks < 4; ++ks) {
          const uint32_t off = sw128(
              (uint32_t)(((2 * jb2 + kjb) * 8 + krow) * 128 + ks * 32 + kk8));
          uint32_t kh4[4], kl4[4];
          ldsm_x4(kh4, sbase + off);
          ldsm_x4(kl4, sbase + 8192 + off);
          mma_bf16(s0p, qh[ks], kh4[0], kh4[1]);
          mma_bf16(s0p, ql[ks], kh4[0], kh4[1]);
          mma_bf16(s0p, qh[ks], kl4[0], kl4[1]);
          mma_bf16(s1p, qh[ks], kh4[2], kh4[3]);
          mma_bf16(s1p, ql[ks], kh4[2], kh4[3]);
          mma_bf16(s1p, qh[ks], kl4[2], kl4[3]);
        }
      }

      const bool diag = (it == ntiles - 1);
      float mx1 = kNegBig, mx2 = kNegBig;
#pragma unroll
      for (int jb = 0; jb < 8; ++jb) {
#pragma unroll
        for (int i = 0; i < 2; ++i) {
          const int jl = jb * 8 + tg * 2 + i;
          const float ma = madd[jl];
          float v1 = sc[jb][i] * kScale + ma;
          float v2 = sc[jb][2 + i] * kScale + ma;
          if (diag) {
            const int jglob = s0 + jl;
            if (jglob > qg1) v1 = kNegBig;
            if (jglob > qg2) v2 = kNegBig;
          }
          sc[jb][i] = v1;
          sc[jb][2 + i] = v2;
          mx1 = fmaxf(mx1, v1);
          mx2 = fmaxf(mx2, v2);
        }
      }
      mx1 = fmaxf(mx1, __shfl_xor_sync(0xffffffffu, mx1, 1));
      mx1 = fmaxf(mx1, __shfl_xor_sync(0xffffffffu, mx1, 2));
      mx2 = fmaxf(mx2, __shfl_xor_sync(0xffffffffu, mx2, 1));
      mx2 = fmaxf(mx2, __shfl_xor_sync(0xffffffffu, mx2, 2));
      const float mn1 = fmaxf(m1, mx1), mn2 = fmaxf(m2, mx2);
      const float al1 = __expf(m1 - mn1), al2 = __expf(m2 - mn2);
      m1 = mn1; m2 = mn2;
      float s1 = 0.0f, s2 = 0.0f;
#pragma unroll
      for (int jb = 0; jb < 8; ++jb) {
        sc[jb][0] = __expf(sc[jb][0] - mn1);
        sc[jb][1] = __expf(sc[jb][1] - mn1);
        sc[jb][2] = __expf(sc[jb][2] - mn2);
        sc[jb][3] = __expf(sc[jb][3] - mn2);
        s1 += sc[jb][0] + sc[jb][1];
        s2 += sc[jb][2] + sc[jb][3];
      }
      s1 += __shfl_xor_sync(0xffffffffu, s1, 1);
      s1 += __shfl_xor_sync(0xffffffffu, s1, 2);
      s2 += __shfl_xor_sync(0xffffffffu, s2, 1);
      s2 += __shfl_xor_sync(0xffffffffu, s2, 2);
      l1 = l1 * al1 + s1;
      l2 = l2 * al2 + s2;
#pragma unroll
      for (int nb = 0; nb < 8; ++nb) {
        O[nb][0] *= al1; O[nb][1] *= al1;
        O[nb][2] *= al2; O[nb][3] *= al2;
      }

      uint32_t ph[4][4], pl[4][4];
#pragma unroll
      for (int ks = 0; ks < 4; ++ks) {
        const int jb0 = 2 * ks, jb1 = 2 * ks + 1;
        split_pack(sc[jb0][0], sc[jb0][1], ph[ks][0], pl[ks][0]);
        split_pack(sc[jb0][2], sc[jb0][3], ph[ks][1], pl[ks][1]);
        split_pack(sc[jb1][0], sc[jb1][1], ph[ks][2], pl[ks][2]);
        split_pack(sc[jb1][2], sc[jb1][3], ph[ks][3], pl[ks][3]);
      }

#pragma unroll
      for (int nb2 = 0; nb2 < 4; ++nb2) {
        float* o0 = O[2 * nb2];
        float* o1 = O[2 * nb2 + 1];
#pragma unroll
        for (int ks = 0; ks < 4; ++ks) {
          const uint32_t off = sw128(
              (uint32_t)((ks * 16 + vrow) * 128 + (2 * nb2 + vnb) * 16));
          uint32_t vh4[4], vl4[4];
          ldsm_x4t(vh4, sbase + 16384 + off);
          ldsm_x4t(vl4, sbase + 24576 + off);
          mma_bf16(o0, ph[ks], vh4[0], vh4[1]);
          mma_bf16(o0, pl[ks], vh4[0], vh4[1]);
          mma_bf16(o0, ph[ks], vl4[0], vl4[1]);
          mma_bf16(o1, ph[ks], vh4[2], vh4[3]);
          mma_bf16(o1, pl[ks], vh4[2], vh4[3]);
          mma_bf16(o1, ph[ks], vl4[2], vl4[3]);
        }
      }
      barteam(barid);
    }

    // ---- team merge (log-sum-exp) ----
    const int rl1 = w * 16 + g, rl2 = rl1 + 8;
    float* mA = (float*)(smem + aM);
    float* lA = (float*)(smem + aL);
    if (tg == 0) {
      mA[team * 64 + rl1] = m1; mA[team * 64 + rl2] = m2;
      lA[team * 64 + rl1] = l1; lA[team * 64 + rl2] = l2;
    }
    __syncthreads();
    const float mo1 = mA[(1 - team) * 64 + rl1];
    const float mo2 = mA[(1 - team) * 64 + rl2];
    const float lo1 = lA[(1 - team) * 64 + rl1];
    const float lo2 = lA[(1 - team) * 64 + rl2];
    const float M1 = fmaxf(m1, mo1), M2 = fmaxf(m2, mo2);
    const float a1 = __expf(m1 - M1), a2 = __expf(m2 - M2);
    const float ao1 = __expf(mo1 - M1), ao2 = __expf(mo2 - M2);
    const float L1 = l1 * a1 + lo1 * ao1;
    const float L2 = l2 * a2 + lo2 * ao2;
    float* osc = (float*)(smem + aOSC);
    if (team == 1) {
#pragma unroll
      for (int nb = 0; nb < 8; ++nb) {
        const int col = nb * 8 + tg * 2;
        osc[rl1 * 64 + col] = O[nb][0] * a1;
        osc[rl1 * 64 + col + 1] = O[nb][1] * a1;
        osc[rl2 * 64 + col] = O[nb][2] * a2;
        osc[rl2 * 64 + col + 1] = O[nb][3] * a2;
      }
    }
    __syncthreads();
    if (team == 0) {
      const float i1 = 1.0f / L1, i2 = 1.0f / L2;
      const size_t r1o = (size_t)(b * kT + qg1) * kHD;
      const size_t r2o = (size_t)(b * kT + qg2) * kHD;
#pragma unroll
      for (int nb = 0; nb < 8; ++nb) {
        const int col = nb * 8 + tg * 2;
        *(float2*)(out + r1o + col) = make_float2(
            (O[nb][0] * a1 + osc[rl1 * 64 + col]) * i1,
            (O[nb][1] * a1 + osc[rl1 * 64 + col + 1]) * i1);
        *(float2*)(out + r2o + col) = make_float2(
            (O[nb][2] * a2 + osc[rl2 * 64 + col]) * i2,
            (O[nb][3] * a2 + osc[rl2 * 64 + col + 1]) * i2);
      }
    }
  }
}

// ---------------------------------------------------------------------------
extern "C" void kernel_launch(void* const* d_in, const int* in_sizes, int n_in,
                              void* d_out, int out_size) {
  const float* x  = (const float*)d_in[0];
  const float* Wq = (const float*)d_in[1];
  const float* Wk = (const float*)d_in[2];
  const float* Wv = (const float*)d_in[3];
  const int*   pm = (const int*)d_in[4];
  float* out = (float*)d_out;

  cudaFuncSetAttribute(proj_kernel, cudaFuncAttributeMaxDynamicSharedMemorySize,
                       kProjSmem);
  cudaFuncSetAttribute(attn_kernel, cudaFuncAttributeMaxDynamicSharedMemorySize,
                       kAttnSmem);

  // Two no-op launches shift the fixed ncu capture window (-s 5 -c 1)
  // onto proj_kernel so the next round finally profiles it.
  dummy_kernel<<<1, 32>>>();
  dummy_kernel<<<1, 32>>>();
  wsplit_kernel<<<96, 256>>>(Wq, Wk, Wv);
  proj_kernel<<<kM / 128, 256, kProjSmem>>>(x);
  attn_kernel<<<dim3(32, kB), 256, kAttnSmem>>>(pm, out);
}